// round 3
// baseline (speedup 1.0000x reference)
#include <cuda_runtime.h>
#include <math.h>

// GWD loss, single fused kernel, smem-staged coalesced loads:
//  - block processes 256-row chunks (grid-stride over chunks)
//  - coalesced float4 loads -> smem, then 1 row/thread from smem
//  - block reduce -> g_partials; last block reduces partials, writes mean
// Counter self-resets -> deterministic across graph replays.

#define NBLOCKS  1184   // 148 SMs * 8
#define NTHREADS 256
#define CHUNK    256    // rows per block-iteration
#define PF4      (CHUNK * 5 / 4)   // 320 float4 per 5-col tensor chunk
#define WF4      (CHUNK / 4)       // 64 float4 per weight chunk

__device__ float g_partials[NBLOCKS];
__device__ unsigned int g_count = 0;

__device__ __forceinline__ float row_loss(
    float xp, float yp, float wp, float hp, float rp,
    float xt, float yt, float wt, float ht, float rt,
    float wgt)
{
    float dx = xp - xt, dy = yp - yt;
    float xyd = dx * dx + dy * dy;

    float cp, sp, ct, st;
    __sincosf(rp, &sp, &cp);
    __sincosf(rt, &st, &ct);

    float w2p = 0.25f * wp * wp, h2p = 0.25f * hp * hp;
    float w2t = 0.25f * wt * wt, h2t = 0.25f * ht * ht;

    float cp2 = cp * cp, sp2 = sp * sp;
    float ct2 = ct * ct, st2 = st * st;

    float a1 = cp2 * w2p + sp2 * h2p;
    float d1 = sp2 * w2p + cp2 * h2p;
    float b1 = cp * sp * (w2p - h2p);

    float a2 = ct2 * w2t + st2 * h2t;
    float d2 = st2 * w2t + ct2 * h2t;
    float b2 = ct * st * (w2t - h2t);

    float trcross = a1 * a2 + 2.0f * b1 * b2 + d1 * d2;
    float prod4   = fabsf(wp * hp * wt * ht);
    float sqdet   = prod4 * 0.0625f;

    float inner = fmaxf(trcross + 2.0f * sqdet, 0.0f);
    float whr   = (w2p + h2p) + (w2t + h2t) - 2.0f * sqrtf(inner);

    float dist  = sqrtf(fmaxf(xyd + whr, 0.0f));
    float scale = sqrtf(sqrtf(prod4));
    dist = log1pf(dist / scale);
    return (1.0f - 1.0f / (1.0f + dist)) * wgt;
}

__global__ __launch_bounds__(NTHREADS)
void gwd_fused_kernel(const float* __restrict__ pred,
                      const float* __restrict__ target,
                      const float* __restrict__ weight,
                      float* __restrict__ out,
                      int n)
{
    __shared__ float s_pred[CHUNK * 5];
    __shared__ float s_targ[CHUNK * 5];
    __shared__ float s_wgt[CHUNK];

    const int tid = threadIdx.x;
    const int nchunks = n / CHUNK;      // full chunks only
    float acc = 0.0f;

    for (int c = blockIdx.x; c < nchunks; c += gridDim.x)
    {
        const float4* pp = (const float4*)(pred   + (long)c * CHUNK * 5);
        const float4* tp = (const float4*)(target + (long)c * CHUNK * 5);
        const float4* wp = (const float4*)(weight + (long)c * CHUNK);

        // coalesced loads: lane i reads 16B segment i
        ((float4*)s_pred)[tid] = pp[tid];
        ((float4*)s_targ)[tid] = tp[tid];
        if (tid < PF4 - NTHREADS) {
            ((float4*)s_pred)[NTHREADS + tid] = pp[NTHREADS + tid];
            ((float4*)s_targ)[NTHREADS + tid] = tp[NTHREADS + tid];
        }
        if (tid < WF4)
            ((float4*)s_wgt)[tid] = wp[tid];
        __syncthreads();

        // one row per thread; stride-5 smem reads, gcd(5,32)=1 -> no conflicts
        const float* p = s_pred + 5 * tid;
        const float* t = s_targ + 5 * tid;
        acc += row_loss(p[0], p[1], p[2], p[3], p[4],
                        t[0], t[1], t[2], t[3], t[4], s_wgt[tid]);
        __syncthreads();
    }

    // tail rows (n % CHUNK), scalar loads by block 0
    int tail_start = nchunks * CHUNK;
    if (blockIdx.x == 0 && tail_start + tid < n) {
        int i = tail_start + tid;
        const float* p = pred + 5 * (long)i;
        const float* t = target + 5 * (long)i;
        acc += row_loss(p[0], p[1], p[2], p[3], p[4],
                        t[0], t[1], t[2], t[3], t[4], weight[i]);
    }

    // block reduction
    __shared__ float s_warp[NTHREADS / 32];
    for (int off = 16; off > 0; off >>= 1)
        acc += __shfl_down_sync(0xFFFFFFFFu, acc, off);
    int lane = tid & 31;
    int wid  = tid >> 5;
    if (lane == 0) s_warp[wid] = acc;
    __syncthreads();

    __shared__ bool s_last;
    if (wid == 0) {
        float v = (lane < NTHREADS / 32) ? s_warp[lane] : 0.0f;
        for (int off = 16; off > 0; off >>= 1)
            v += __shfl_down_sync(0xFFFFFFFFu, v, off);
        if (lane == 0) {
            g_partials[blockIdx.x] = v;
            __threadfence();
            unsigned int done = atomicAdd(&g_count, 1u);
            s_last = (done == gridDim.x - 1);
        }
    }
    __syncthreads();

    // last block reduces all partials (fixed order -> deterministic)
    if (s_last) {
        float v = 0.0f;
        for (int i = tid; i < NBLOCKS; i += NTHREADS)
            v += g_partials[i];
        for (int off = 16; off > 0; off >>= 1)
            v += __shfl_down_sync(0xFFFFFFFFu, v, off);
        if (lane == 0) s_warp[wid] = v;
        __syncthreads();
        if (wid == 0) {
            float r = (lane < NTHREADS / 32) ? s_warp[lane] : 0.0f;
            for (int off = 16; off > 0; off >>= 1)
                r += __shfl_down_sync(0xFFFFFFFFu, r, off);
            if (lane == 0) {
                out[0] = r / (float)n;
                g_count = 0;   // reset for next graph replay
            }
        }
    }
}

extern "C" void kernel_launch(void* const* d_in, const int* in_sizes, int n_in,
                              void* d_out, int out_size)
{
    const float* pred   = (const float*)d_in[0];
    const float* target = (const float*)d_in[1];
    const float* weight = (const float*)d_in[2];
    float* out = (float*)d_out;

    int n = in_sizes[2];  // weight has N elements

    gwd_fused_kernel<<<NBLOCKS, NTHREADS>>>(pred, target, weight, out, n);
}

// round 4
// speedup vs baseline: 1.1366x; 1.1366x over previous
#include <cuda_runtime.h>
#include <math.h>

// GWD loss, single fused kernel:
//  - scalar stride-5 loads (warp's 5 LDGs cover the same 5 contiguous lines
//    -> aggregate-coalesced, 5-way MLP, no barriers in the loop)
//  - block reduce -> g_partials; last finished block reduces, writes mean
// Counter self-resets -> deterministic across graph replays.

#define NBLOCKS  1184   // 148 SMs * 8
#define NTHREADS 256

__device__ float g_partials[NBLOCKS];
__device__ unsigned int g_count = 0;

__device__ __forceinline__ float row_loss(
    float xp, float yp, float wp, float hp, float rp,
    float xt, float yt, float wt, float ht, float rt,
    float wgt)
{
    float dx = xp - xt, dy = yp - yt;
    float xyd = dx * dx + dy * dy;

    float cp, sp, ct, st;
    __sincosf(rp, &sp, &cp);
    __sincosf(rt, &st, &ct);

    float w2p = 0.25f * wp * wp, h2p = 0.25f * hp * hp;
    float w2t = 0.25f * wt * wt, h2t = 0.25f * ht * ht;

    float cp2 = cp * cp, sp2 = sp * sp;
    float ct2 = ct * ct, st2 = st * st;

    float a1 = cp2 * w2p + sp2 * h2p;
    float d1 = sp2 * w2p + cp2 * h2p;
    float b1 = cp * sp * (w2p - h2p);

    float a2 = ct2 * w2t + st2 * h2t;
    float d2 = st2 * w2t + ct2 * h2t;
    float b2 = ct * st * (w2t - h2t);

    float trcross = a1 * a2 + 2.0f * b1 * b2 + d1 * d2;
    float prod4   = fabsf(wp * hp * wt * ht);
    float sqdet   = prod4 * 0.0625f;

    float inner = fmaxf(trcross + 2.0f * sqdet, 0.0f);
    float whr   = (w2p + h2p) + (w2t + h2t) - 2.0f * sqrtf(inner);

    float dist  = sqrtf(fmaxf(xyd + whr, 0.0f));
    float scale = sqrtf(sqrtf(prod4));
    dist = log1pf(dist / scale);
    return (1.0f - 1.0f / (1.0f + dist)) * wgt;
}

__global__ __launch_bounds__(NTHREADS)
void gwd_fused_kernel(const float* __restrict__ pred,
                      const float* __restrict__ target,
                      const float* __restrict__ weight,
                      float* __restrict__ out,
                      int n)
{
    float acc = 0.0f;
    for (int i = blockIdx.x * NTHREADS + threadIdx.x; i < n;
         i += gridDim.x * NTHREADS)
    {
        const float* p = pred   + 5 * (long)i;
        const float* t = target + 5 * (long)i;
        acc += row_loss(p[0], p[1], p[2], p[3], p[4],
                        t[0], t[1], t[2], t[3], t[4], weight[i]);
    }

    // block reduction
    __shared__ float s_warp[NTHREADS / 32];
    for (int off = 16; off > 0; off >>= 1)
        acc += __shfl_down_sync(0xFFFFFFFFu, acc, off);
    int lane = threadIdx.x & 31;
    int wid  = threadIdx.x >> 5;
    if (lane == 0) s_warp[wid] = acc;
    __syncthreads();

    __shared__ bool s_last;
    if (wid == 0) {
        float v = (lane < NTHREADS / 32) ? s_warp[lane] : 0.0f;
        for (int off = 16; off > 0; off >>= 1)
            v += __shfl_down_sync(0xFFFFFFFFu, v, off);
        if (lane == 0) {
            g_partials[blockIdx.x] = v;
            __threadfence();
            unsigned int done = atomicAdd(&g_count, 1u);
            s_last = (done == gridDim.x - 1);
        }
    }
    __syncthreads();

    // last block reduces all partials (fixed order -> deterministic)
    if (s_last) {
        float v = 0.0f;
        for (int i = threadIdx.x; i < NBLOCKS; i += NTHREADS)
            v += g_partials[i];
        for (int off = 16; off > 0; off >>= 1)
            v += __shfl_down_sync(0xFFFFFFFFu, v, off);
        if (lane == 0) s_warp[wid] = v;
        __syncthreads();
        if (wid == 0) {
            float r = (lane < NTHREADS / 32) ? s_warp[lane] : 0.0f;
            for (int off = 16; off > 0; off >>= 1)
                r += __shfl_down_sync(0xFFFFFFFFu, r, off);
            if (lane == 0) {
                out[0] = r / (float)n;
                g_count = 0;   // reset for next graph replay
            }
        }
    }
}

extern "C" void kernel_launch(void* const* d_in, const int* in_sizes, int n_in,
                              void* d_out, int out_size)
{
    const float* pred   = (const float*)d_in[0];
    const float* target = (const float*)d_in[1];
    const float* weight = (const float*)d_in[2];
    float* out = (float*)d_out;

    int n = in_sizes[2];  // weight has N elements

    gwd_fused_kernel<<<NBLOCKS, NTHREADS>>>(pred, target, weight, out, n);
}

// round 5
// speedup vs baseline: 1.2598x; 1.1084x over previous
#include <cuda_runtime.h>
#include <math.h>

// GWD loss, single fused kernel:
//  - scalar stride-5 loads, 2 independent rows per loop iteration (22-deep MLP)
//  - approx MUFU math (sqrt/rcp/lg2/rsqrt) -- tolerance is 1e-3, we have 1e-6
//  - block reduce -> g_partials; last finished block reduces, writes mean
// Counter self-resets -> deterministic across graph replays.

#define NBLOCKS  1184   // 148 SMs * 8
#define NTHREADS 256

__device__ float g_partials[NBLOCKS];
__device__ unsigned int g_count = 0;

__device__ __forceinline__ float f_sqrt(float x) {
    float r; asm("sqrt.approx.f32 %0, %1;" : "=f"(r) : "f"(x)); return r;
}
__device__ __forceinline__ float f_rsqrt(float x) {
    float r; asm("rsqrt.approx.f32 %0, %1;" : "=f"(r) : "f"(x)); return r;
}
__device__ __forceinline__ float f_rcp(float x) {
    float r; asm("rcp.approx.f32 %0, %1;" : "=f"(r) : "f"(x)); return r;
}
__device__ __forceinline__ float f_lg2(float x) {
    float r; asm("lg2.approx.f32 %0, %1;" : "=f"(r) : "f"(x)); return r;
}

__device__ __forceinline__ float row_loss(
    float xp, float yp, float wp, float hp, float rp,
    float xt, float yt, float wt, float ht, float rt,
    float wgt)
{
    float dx = xp - xt, dy = yp - yt;
    float xyd = dx * dx + dy * dy;

    float cp, sp, ct, st;
    __sincosf(rp, &sp, &cp);
    __sincosf(rt, &st, &ct);

    float w2p = 0.25f * wp * wp, h2p = 0.25f * hp * hp;
    float w2t = 0.25f * wt * wt, h2t = 0.25f * ht * ht;

    float cp2 = cp * cp, sp2 = sp * sp;
    float ct2 = ct * ct, st2 = st * st;

    float a1 = cp2 * w2p + sp2 * h2p;
    float d1 = sp2 * w2p + cp2 * h2p;
    float b1 = cp * sp * (w2p - h2p);

    float a2 = ct2 * w2t + st2 * h2t;
    float d2 = st2 * w2t + ct2 * h2t;
    float b2 = ct * st * (w2t - h2t);

    float trcross = a1 * a2 + 2.0f * b1 * b2 + d1 * d2;
    float prod4   = fabsf(wp * hp * wt * ht);
    float sqdet   = prod4 * 0.0625f;

    float inner = fmaxf(trcross + 2.0f * sqdet, 0.0f);
    float whr   = (w2p + h2p) + (w2t + h2t) - 2.0f * f_sqrt(inner);

    float dist  = f_sqrt(fmaxf(xyd + whr, 0.0f));
    // inv_scale = prod4^(-1/4) = rsqrt(sqrt(prod4))
    float inv_scale = f_rsqrt(f_sqrt(prod4));
    dist = dist * inv_scale;

    // log1p(dist) = lg2(1 + dist) * ln(2)
    float ln1p = f_lg2(1.0f + dist) * 0.6931471805599453f;
    // loss = 1 - 1/(1 + ln1p)
    float loss = 1.0f - f_rcp(1.0f + ln1p);
    return loss * wgt;
}

__global__ __launch_bounds__(NTHREADS)
void gwd_fused_kernel(const float* __restrict__ pred,
                      const float* __restrict__ target,
                      const float* __restrict__ weight,
                      float* __restrict__ out,
                      int n)
{
    const int stride = gridDim.x * NTHREADS;
    float acc = 0.0f;

    int i = blockIdx.x * NTHREADS + threadIdx.x;
    // two independent rows per iteration -> 22 LDGs in flight
    for (; i + stride < n; i += 2 * stride)
    {
        int j = i + stride;
        const float* p0 = pred   + 5 * (long)i;
        const float* t0 = target + 5 * (long)i;
        const float* p1 = pred   + 5 * (long)j;
        const float* t1 = target + 5 * (long)j;

        float pa = p0[0], pb = p0[1], pc = p0[2], pd = p0[3], pe = p0[4];
        float ta = t0[0], tb = t0[1], tc = t0[2], td = t0[3], te = t0[4];
        float qa = p1[0], qb = p1[1], qc = p1[2], qd = p1[3], qe = p1[4];
        float ua = t1[0], ub = t1[1], uc = t1[2], ud = t1[3], ue = t1[4];
        float w0 = weight[i], w1 = weight[j];

        acc += row_loss(pa, pb, pc, pd, pe, ta, tb, tc, td, te, w0);
        acc += row_loss(qa, qb, qc, qd, qe, ua, ub, uc, ud, ue, w1);
    }
    if (i < n) {
        const float* p = pred   + 5 * (long)i;
        const float* t = target + 5 * (long)i;
        acc += row_loss(p[0], p[1], p[2], p[3], p[4],
                        t[0], t[1], t[2], t[3], t[4], weight[i]);
    }

    // block reduction
    __shared__ float s_warp[NTHREADS / 32];
    for (int off = 16; off > 0; off >>= 1)
        acc += __shfl_down_sync(0xFFFFFFFFu, acc, off);
    int lane = threadIdx.x & 31;
    int wid  = threadIdx.x >> 5;
    if (lane == 0) s_warp[wid] = acc;
    __syncthreads();

    __shared__ bool s_last;
    if (wid == 0) {
        float v = (lane < NTHREADS / 32) ? s_warp[lane] : 0.0f;
        for (int off = 16; off > 0; off >>= 1)
            v += __shfl_down_sync(0xFFFFFFFFu, v, off);
        if (lane == 0) {
            g_partials[blockIdx.x] = v;
            __threadfence();
            unsigned int done = atomicAdd(&g_count, 1u);
            s_last = (done == gridDim.x - 1);
        }
    }
    __syncthreads();

    // last block reduces all partials (fixed order -> deterministic)
    if (s_last) {
        float v = 0.0f;
        for (int k = threadIdx.x; k < NBLOCKS; k += NTHREADS)
            v += g_partials[k];
        for (int off = 16; off > 0; off >>= 1)
            v += __shfl_down_sync(0xFFFFFFFFu, v, off);
        if (lane == 0) s_warp[wid] = v;
        __syncthreads();
        if (wid == 0) {
            float r = (lane < NTHREADS / 32) ? s_warp[lane] : 0.0f;
            for (int off = 16; off > 0; off >>= 1)
                r += __shfl_down_sync(0xFFFFFFFFu, r, off);
            if (lane == 0) {
                out[0] = r / (float)n;
                g_count = 0;   // reset for next graph replay
            }
        }
    }
}

extern "C" void kernel_launch(void* const* d_in, const int* in_sizes, int n_in,
                              void* d_out, int out_size)
{
    const float* pred   = (const float*)d_in[0];
    const float* target = (const float*)d_in[1];
    const float* weight = (const float*)d_in[2];
    float* out = (float*)d_out;

    int n = in_sizes[2];  // weight has N elements

    gwd_fused_kernel<<<NBLOCKS, NTHREADS>>>(pred, target, weight, out, n);
}

// round 6
// speedup vs baseline: 1.2765x; 1.0133x over previous
#include <cuda_runtime.h>
#include <math.h>

// GWD loss, single fused kernel, cp.async double-buffered smem staging:
//  - 256-row chunks; 704 coalesced 16B cp.async per chunk (1 wavefront/line)
//  - prefetch chunk c+grid while computing chunk c (2-stage pipeline)
//  - compute 1 row/thread from smem (stride-5, conflict-free), approx math
//  - block reduce -> g_partials; last finished block reduces, writes mean

#define NBLOCKS  1184   // 148 SMs * 8
#define NTHREADS 256
#define CHUNK    256
#define PRED_F4  320    // CHUNK*5/4
#define TOT_F4   704    // pred 320 + targ 320 + wgt 64

__device__ float g_partials[NBLOCKS];
__device__ unsigned int g_count = 0;

__device__ __forceinline__ float f_sqrt(float x) {
    float r; asm("sqrt.approx.f32 %0, %1;" : "=f"(r) : "f"(x)); return r;
}
__device__ __forceinline__ float f_rsqrt(float x) {
    float r; asm("rsqrt.approx.f32 %0, %1;" : "=f"(r) : "f"(x)); return r;
}
__device__ __forceinline__ float f_rcp(float x) {
    float r; asm("rcp.approx.f32 %0, %1;" : "=f"(r) : "f"(x)); return r;
}
__device__ __forceinline__ float f_lg2(float x) {
    float r; asm("lg2.approx.f32 %0, %1;" : "=f"(r) : "f"(x)); return r;
}

__device__ __forceinline__ void cp16(float4* smem, const float4* gmem) {
    unsigned saddr = (unsigned)__cvta_generic_to_shared(smem);
    asm volatile("cp.async.cg.shared.global [%0], [%1], 16;\n"
                 :: "r"(saddr), "l"(gmem));
}

__device__ __forceinline__ float row_loss(
    float xp, float yp, float wp, float hp, float rp,
    float xt, float yt, float wt, float ht, float rt,
    float wgt)
{
    float dx = xp - xt, dy = yp - yt;
    float xyd = dx * dx + dy * dy;

    float cp, sp, ct, st;
    __sincosf(rp, &sp, &cp);
    __sincosf(rt, &st, &ct);

    float w2p = 0.25f * wp * wp, h2p = 0.25f * hp * hp;
    float w2t = 0.25f * wt * wt, h2t = 0.25f * ht * ht;

    float cp2 = cp * cp, sp2 = sp * sp;
    float ct2 = ct * ct, st2 = st * st;

    float a1 = cp2 * w2p + sp2 * h2p;
    float d1 = sp2 * w2p + cp2 * h2p;
    float b1 = cp * sp * (w2p - h2p);

    float a2 = ct2 * w2t + st2 * h2t;
    float d2 = st2 * w2t + ct2 * h2t;
    float b2 = ct * st * (w2t - h2t);

    float trcross = a1 * a2 + 2.0f * b1 * b2 + d1 * d2;
    float prod4   = fabsf(wp * hp * wt * ht);
    float sqdet   = prod4 * 0.0625f;

    float inner = fmaxf(trcross + 2.0f * sqdet, 0.0f);
    float whr   = (w2p + h2p) + (w2t + h2t) - 2.0f * f_sqrt(inner);

    float dist  = f_sqrt(fmaxf(xyd + whr, 0.0f));
    float inv_scale = f_rsqrt(f_sqrt(prod4));   // prod4^(-1/4)
    dist = dist * inv_scale;

    float ln1p = f_lg2(1.0f + dist) * 0.6931471805599453f;
    float loss = 1.0f - f_rcp(1.0f + ln1p);
    return loss * wgt;
}

__global__ __launch_bounds__(NTHREADS)
void gwd_fused_kernel(const float* __restrict__ pred,
                      const float* __restrict__ target,
                      const float* __restrict__ weight,
                      float* __restrict__ out,
                      int n)
{
    // [0..319]=pred f4, [320..639]=targ f4, [640..703]=weight f4
    __shared__ float4 s_buf[2][TOT_F4];

    const int tid = threadIdx.x;
    const int nchunks = n / CHUNK;
    float acc = 0.0f;

    // ---- async load issue for one chunk ----
    auto issue = [&](int c, int b) {
        const float4* gp = (const float4*)(pred   + (long)c * CHUNK * 5);
        const float4* gt = (const float4*)(target + (long)c * CHUNK * 5);
        const float4* gw = (const float4*)(weight + (long)c * CHUNK);
        cp16(&s_buf[b][tid],        &gp[tid]);            // pred 0..255
        cp16(&s_buf[b][320 + tid],  &gt[tid]);            // targ 0..255
        if (tid < PRED_F4 - NTHREADS) {                   // 64 threads
            cp16(&s_buf[b][256 + tid],       &gp[256 + tid]);  // pred 256..319
            cp16(&s_buf[b][320 + 256 + tid], &gt[256 + tid]);  // targ 256..319
            cp16(&s_buf[b][640 + tid],       &gw[tid]);        // weight
        }
    };

    int c = blockIdx.x;
    int b = 0;
    if (c < nchunks) issue(c, 0);
    asm volatile("cp.async.commit_group;\n" ::: "memory");

    for (; c < nchunks; c += gridDim.x)
    {
        int cn = c + gridDim.x;
        if (cn < nchunks) issue(cn, b ^ 1);
        asm volatile("cp.async.commit_group;\n" ::: "memory");
        asm volatile("cp.async.wait_group 1;\n" ::: "memory");
        __syncthreads();   // buffer b data visible to all

        const float* p = (const float*)&s_buf[b][0]       + 5 * tid;
        const float* t = (const float*)&s_buf[b][320]     + 5 * tid;
        const float* w = (const float*)&s_buf[b][640];
        acc += row_loss(p[0], p[1], p[2], p[3], p[4],
                        t[0], t[1], t[2], t[3], t[4], w[tid]);

        __syncthreads();   // all done with buffer b before it is overwritten
        b ^= 1;
    }

    // tail rows (n % CHUNK): block 0, scalar loads
    int tail_start = nchunks * CHUNK;
    if (blockIdx.x == 0 && tail_start + tid < n) {
        int i = tail_start + tid;
        const float* p = pred + 5 * (long)i;
        const float* t = target + 5 * (long)i;
        acc += row_loss(p[0], p[1], p[2], p[3], p[4],
                        t[0], t[1], t[2], t[3], t[4], weight[i]);
    }

    // block reduction
    __shared__ float s_warp[NTHREADS / 32];
    for (int off = 16; off > 0; off >>= 1)
        acc += __shfl_down_sync(0xFFFFFFFFu, acc, off);
    int lane = tid & 31;
    int wid  = tid >> 5;
    if (lane == 0) s_warp[wid] = acc;
    __syncthreads();

    __shared__ bool s_last;
    if (wid == 0) {
        float v = (lane < NTHREADS / 32) ? s_warp[lane] : 0.0f;
        for (int off = 16; off > 0; off >>= 1)
            v += __shfl_down_sync(0xFFFFFFFFu, v, off);
        if (lane == 0) {
            g_partials[blockIdx.x] = v;
            __threadfence();
            unsigned int done = atomicAdd(&g_count, 1u);
            s_last = (done == gridDim.x - 1);
        }
    }
    __syncthreads();

    if (s_last) {
        float v = 0.0f;
        for (int k = tid; k < NBLOCKS; k += NTHREADS)
            v += g_partials[k];
        for (int off = 16; off > 0; off >>= 1)
            v += __shfl_down_sync(0xFFFFFFFFu, v, off);
        if (lane == 0) s_warp[wid] = v;
        __syncthreads();
        if (wid == 0) {
            float r = (lane < NTHREADS / 32) ? s_warp[lane] : 0.0f;
            for (int off = 16; off > 0; off >>= 1)
                r += __shfl_down_sync(0xFFFFFFFFu, r, off);
            if (lane == 0) {
                out[0] = r / (float)n;
                g_count = 0;   // reset for next graph replay
            }
        }
    }
}

extern "C" void kernel_launch(void* const* d_in, const int* in_sizes, int n_in,
                              void* d_out, int out_size)
{
    const float* pred   = (const float*)d_in[0];
    const float* target = (const float*)d_in[1];
    const float* weight = (const float*)d_in[2];
    float* out = (float*)d_out;

    int n = in_sizes[2];  // weight has N elements

    gwd_fused_kernel<<<NBLOCKS, NTHREADS>>>(pred, target, weight, out, n);
}